// round 2
// baseline (speedup 1.0000x reference)
#include <cuda_runtime.h>
#include <math.h>

#define NMAX 8192

// Per-gaussian precomputed params (SoA of float4 for single-LDG.128 access).
__device__ float4 g_bbox[NMAX];  // (min_u, max_u, min_v, max_v)
__device__ float4 g_geom[NMAX];  // (u, v, z, op)
__device__ float4 g_cov [NMAX];  // (ia, ib+ic, id, unused)
__device__ float4 g_col [NMAX];  // (r, g, b, unused)

__device__ __forceinline__ float sigmoidf_(float x) {
    return 1.0f / (1.0f + expf(-x));
}

__global__ void preprocess_kernel(
    const float* __restrict__ means,      // (N,3)
    const float* __restrict__ scales,     // (N,3)
    const float* __restrict__ rots,       // (N,4)
    const float* __restrict__ opacities,  // (N,1)
    const float* __restrict__ features,   // (N,3)
    const float* __restrict__ pose,       // (4,4) row-major
    const float* __restrict__ focal_p,
    const float* __restrict__ cx_p,
    const float* __restrict__ cy_p,
    int N)
{
    int n = blockIdx.x * blockDim.x + threadIdx.x;
    if (n >= N) return;

    const float f  = focal_p[0];
    const float cx = cx_p[0];
    const float cy = cy_p[0];

    // scales -> sc = exp(scales)
    float sc0 = expf(scales[n*3 + 0]);
    float sc1 = expf(scales[n*3 + 1]);
    float sc2 = expf(scales[n*3 + 2]);

    // quaternion -> rotation matrix M (3x3)
    float qw = rots[n*4 + 0];
    float qx = rots[n*4 + 1];
    float qy = rots[n*4 + 2];
    float qz = rots[n*4 + 3];
    float two_s = 2.0f / (qw*qw + qx*qx + qy*qy + qz*qz);
    float xx = qx*qx*two_s, xy = qx*qy*two_s, xz = qx*qz*two_s;
    float yw = qy*qw*two_s, yy = qy*qy*two_s, yz = qy*qz*two_s;
    float zw = qz*qw*two_s, zz = qz*qz*two_s, xw = qx*qw*two_s;
    float M00 = 1.0f - (yy + zz), M01 = xy - zw,          M02 = xz + yw;
    float M10 = xy + zw,          M11 = 1.0f - (xx + zz), M12 = yz - xw;
    float M20 = xz - yw,          M21 = yz + xw,          M22 = 1.0f - (xx + yy);

    // camera
    float R00 = pose[0], R01 = pose[1], R02 = pose[2],  t0 = pose[3];
    float R10 = pose[4], R11 = pose[5], R12 = pose[6],  t1 = pose[7];
    float R20 = pose[8], R21 = pose[9], R22 = pose[10], t2 = pose[11];

    float mx = means[n*3 + 0], my = means[n*3 + 1], mz = means[n*3 + 2];
    // means_cam = means @ R.T + t  (row n: R * mean + t)
    float pcx = R00*mx + R01*my + R02*mz + t0;
    float pcy = R10*mx + R11*my + R12*mz + t1;
    float pcz = R20*mx + R21*my + R22*mz + t2;

    float z = pcz;
    float u = pcx / z * f + cx;
    float v = pcy / z * f + cy;

    // J = [[f,0,-cx],[0,f,-cy],[0,0,1]] @ R  (only rows 0,1 needed)
    float J00 = f*R00 - cx*R20, J01 = f*R01 - cx*R21, J02 = f*R02 - cx*R22;
    float J10 = f*R10 - cy*R20, J11 = f*R11 - cy*R21, J12 = f*R12 - cy*R22;

    // V2[i][k] = (J[i,:] . M[:,k]) * sc[k]
    float V00 = (J00*M00 + J01*M10 + J02*M20) * sc0;
    float V01 = (J00*M01 + J01*M11 + J02*M21) * sc1;
    float V02 = (J00*M02 + J01*M12 + J02*M22) * sc2;
    float V10 = (J10*M00 + J11*M10 + J12*M20) * sc0;
    float V11 = (J10*M01 + J11*M11 + J12*M21) * sc1;
    float V12 = (J10*M02 + J11*M12 + J12*M22) * sc2;

    float inv_zz = 1.0f / (z * z);
    float a = (V00*V00 + V01*V01 + V02*V02) * inv_zz;
    float b = (V00*V10 + V01*V11 + V02*V12) * inv_zz;
    float d = (V10*V10 + V11*V11 + V12*V12) * inv_zz;

    float det = a*d - b*b;
    float ia  = d / det;
    float ibc = (-b - b) / det;   // ib + ic = -2b/det
    float idd = a / det;

    float op = sigmoidf_(opacities[n]);
    float cr = sigmoidf_(features[n*3 + 0]);
    float cg = sigmoidf_(features[n*3 + 1]);
    float cb = sigmoidf_(features[n*3 + 2]);

    float smax = fmaxf(sc0, fmaxf(sc1, sc2));
    float r = smax * f / z * 3.0f;

    float min_u = fmaxf(0.0f, truncf(u - r));
    float max_u = truncf(u + r);
    float min_v = fmaxf(0.0f, truncf(v - r));
    float max_v = truncf(v + r);

    g_bbox[n] = make_float4(min_u, max_u, min_v, max_v);
    g_geom[n] = make_float4(u, v, z, op);
    g_cov [n] = make_float4(ia, ibc, idd, 0.0f);
    g_col [n] = make_float4(cr, cg, cb, 0.0f);
}

__global__ __launch_bounds__(128, 8)
void render_kernel(float* __restrict__ out, int N, int W, int H)
{
    int px = blockIdx.x * blockDim.x + threadIdx.x;
    int py = blockIdx.y * blockDim.y + threadIdx.y;
    if (px >= W || py >= H) return;

    float pxf = (float)px;
    float pyf = (float)py;

    float ir = 0.0f, ig = 0.0f, ib = 0.0f;
    float alpha_buf = 0.0f;
    float depth_buf = __int_as_float(0x7f800000);  // +inf

    for (int n = 0; n < N; n++) {
        float4 bb = __ldg(&g_bbox[n]);
        // in_box: px >= min_u && px <= max_u && py >= min_v && py <= max_v
        if (pxf >= bb.x && pxf <= bb.y && pyf >= bb.z && pyf <= bb.w) {
            float4 gm = __ldg(&g_geom[n]);
            float4 cv = __ldg(&g_cov[n]);
            float dx = pxf - gm.x;
            float dy = pyf - gm.y;
            float dist_sq = cv.x*dx*dx + cv.y*dx*dy + cv.z*dy*dy;
            // NaN dist_sq -> comparison false, same as reference mask
            if (dist_sq < 9.0f && gm.z < depth_buf) {
                float alpha = gm.w * expf(-0.5f * dist_sq);
                float na = alpha * (1.0f - alpha_buf);
                float4 cl = __ldg(&g_col[n]);
                float om = 1.0f - na;
                ir = ir * om + cl.x * na;
                ig = ig * om + cl.y * na;
                ib = ib * om + cl.z * na;
                alpha_buf += na;
                depth_buf = gm.z;
            }
        }
    }

    int base = (py * W + px) * 3;
    out[base + 0] = ir;
    out[base + 1] = ig;
    out[base + 2] = ib;
}

extern "C" void kernel_launch(void* const* d_in, const int* in_sizes, int n_in,
                              void* d_out, int out_size)
{
    const float* means     = (const float*)d_in[0];
    const float* scales    = (const float*)d_in[1];
    const float* rots      = (const float*)d_in[2];
    const float* opacities = (const float*)d_in[3];
    const float* features  = (const float*)d_in[4];
    const float* pose      = (const float*)d_in[5];
    const float* focal_p   = (const float*)d_in[6];
    const float* cx_p      = (const float*)d_in[7];
    const float* cy_p      = (const float*)d_in[8];

    int N = in_sizes[0] / 3;

    // Derive (square) image dims from output size: out = H*W*3 floats.
    int hw = out_size / 3;
    int W = (int)(sqrtf((float)hw) + 0.5f);
    int H = hw / W;

    preprocess_kernel<<<(N + 255) / 256, 256>>>(
        means, scales, rots, opacities, features, pose,
        focal_p, cx_p, cy_p, N);

    dim3 blk(16, 8);
    dim3 grd((W + blk.x - 1) / blk.x, (H + blk.y - 1) / blk.y);
    render_kernel<<<grd, blk>>>((float*)d_out, N, W, H);
}

// round 3
// speedup vs baseline: 3.1722x; 3.1722x over previous
#include <cuda_runtime.h>
#include <math.h>

#define NMAX 8192
#define CHUNK 128

// Per-gaussian precomputed params (SoA of float4 for coalesced LDG.128 staging).
__device__ float4 g_bbox[NMAX];  // (min_u, max_u, min_v, max_v)
__device__ float4 g_geom[NMAX];  // (u, v, z, op)
__device__ float4 g_cov [NMAX];  // (ia, ib+ic, id, unused)
__device__ float4 g_col [NMAX];  // (r, g, b, unused)

__device__ __forceinline__ float sigmoidf_(float x) {
    return 1.0f / (1.0f + expf(-x));
}

__global__ void preprocess_kernel(
    const float* __restrict__ means,      // (N,3)
    const float* __restrict__ scales,     // (N,3)
    const float* __restrict__ rots,       // (N,4)
    const float* __restrict__ opacities,  // (N,1)
    const float* __restrict__ features,   // (N,3)
    const float* __restrict__ pose,       // (4,4) row-major
    const float* __restrict__ focal_p,
    const float* __restrict__ cx_p,
    const float* __restrict__ cy_p,
    int N)
{
    int n = blockIdx.x * blockDim.x + threadIdx.x;
    if (n >= N) return;

    const float f  = focal_p[0];
    const float cx = cx_p[0];
    const float cy = cy_p[0];

    float sc0 = expf(scales[n*3 + 0]);
    float sc1 = expf(scales[n*3 + 1]);
    float sc2 = expf(scales[n*3 + 2]);

    float qw = rots[n*4 + 0];
    float qx = rots[n*4 + 1];
    float qy = rots[n*4 + 2];
    float qz = rots[n*4 + 3];
    float two_s = 2.0f / (qw*qw + qx*qx + qy*qy + qz*qz);
    float xx = qx*qx*two_s, xy = qx*qy*two_s, xz = qx*qz*two_s;
    float yw = qy*qw*two_s, yy = qy*qy*two_s, yz = qy*qz*two_s;
    float zw = qz*qw*two_s, zz = qz*qz*two_s, xw = qx*qw*two_s;
    float M00 = 1.0f - (yy + zz), M01 = xy - zw,          M02 = xz + yw;
    float M10 = xy + zw,          M11 = 1.0f - (xx + zz), M12 = yz - xw;
    float M20 = xz - yw,          M21 = yz + xw,          M22 = 1.0f - (xx + yy);

    float R00 = pose[0], R01 = pose[1], R02 = pose[2],  t0 = pose[3];
    float R10 = pose[4], R11 = pose[5], R12 = pose[6],  t1 = pose[7];
    float R20 = pose[8], R21 = pose[9], R22 = pose[10], t2 = pose[11];

    float mx = means[n*3 + 0], my = means[n*3 + 1], mz = means[n*3 + 2];
    float pcx = R00*mx + R01*my + R02*mz + t0;
    float pcy = R10*mx + R11*my + R12*mz + t1;
    float pcz = R20*mx + R21*my + R22*mz + t2;

    float z = pcz;
    float u = pcx / z * f + cx;
    float v = pcy / z * f + cy;

    float J00 = f*R00 - cx*R20, J01 = f*R01 - cx*R21, J02 = f*R02 - cx*R22;
    float J10 = f*R10 - cy*R20, J11 = f*R11 - cy*R21, J12 = f*R12 - cy*R22;

    float V00 = (J00*M00 + J01*M10 + J02*M20) * sc0;
    float V01 = (J00*M01 + J01*M11 + J02*M21) * sc1;
    float V02 = (J00*M02 + J01*M12 + J02*M22) * sc2;
    float V10 = (J10*M00 + J11*M10 + J12*M20) * sc0;
    float V11 = (J10*M01 + J11*M11 + J12*M21) * sc1;
    float V12 = (J10*M02 + J11*M12 + J12*M22) * sc2;

    float inv_zz = 1.0f / (z * z);
    float a = (V00*V00 + V01*V01 + V02*V02) * inv_zz;
    float b = (V00*V10 + V01*V11 + V02*V12) * inv_zz;
    float d = (V10*V10 + V11*V11 + V12*V12) * inv_zz;

    float det = a*d - b*b;
    float ia  = d / det;
    float ibc = (-b - b) / det;   // ib + ic = -2b/det
    float idd = a / det;

    float op = sigmoidf_(opacities[n]);
    float cr = sigmoidf_(features[n*3 + 0]);
    float cg = sigmoidf_(features[n*3 + 1]);
    float cb = sigmoidf_(features[n*3 + 2]);

    float smax = fmaxf(sc0, fmaxf(sc1, sc2));
    float r = smax * f / z * 3.0f;

    float min_u = fmaxf(0.0f, truncf(u - r));
    float max_u = truncf(u + r);
    float min_v = fmaxf(0.0f, truncf(v - r));
    float max_v = truncf(v + r);

    g_bbox[n] = make_float4(min_u, max_u, min_v, max_v);
    g_geom[n] = make_float4(u, v, z, op);
    g_cov [n] = make_float4(ia, ibc, idd, 0.0f);
    g_col [n] = make_float4(cr, cg, cb, 0.0f);
}

__global__ __launch_bounds__(128, 8)
void render_kernel(float* __restrict__ out, int N, int W, int H)
{
    __shared__ float4 s_bb [CHUNK];
    __shared__ float4 s_gm [CHUNK];
    __shared__ float4 s_cv [CHUNK];
    __shared__ float4 s_cl [CHUNK];

    int tid = threadIdx.y * blockDim.x + threadIdx.x;
    int px = blockIdx.x * blockDim.x + threadIdx.x;
    int py = blockIdx.y * blockDim.y + threadIdx.y;
    bool valid = (px < W) && (py < H);

    float pxf = (float)px;
    float pyf = (float)py;

    float ir = 0.0f, ig = 0.0f, ib = 0.0f;
    float alpha_buf = 0.0f;
    float depth_buf = __int_as_float(0x7f800000);  // +inf

    for (int base = 0; base < N; base += CHUNK) {
        int m = N - base;
        if (m > CHUNK) m = CHUNK;

        // Cooperative coalesced staging: 128 threads x 4 LDG.128 in flight.
        if (tid < m) {
            s_bb[tid] = g_bbox[base + tid];
            s_gm[tid] = g_geom[base + tid];
            s_cv[tid] = g_cov [base + tid];
            s_cl[tid] = g_col [base + tid];
        }
        __syncthreads();

        #pragma unroll 4
        for (int i = 0; i < m; i++) {
            float4 bb = s_bb[i];
            if (pxf >= bb.x && pxf <= bb.y && pyf >= bb.z && pyf <= bb.w) {
                float4 gm = s_gm[i];
                float4 cv = s_cv[i];
                float dx = pxf - gm.x;
                float dy = pyf - gm.y;
                float dist_sq = cv.x*dx*dx + cv.y*dx*dy + cv.z*dy*dy;
                // NaN dist_sq -> comparison false, same as reference mask
                if (dist_sq < 9.0f && gm.z < depth_buf) {
                    float alpha = gm.w * __expf(-0.5f * dist_sq);
                    float na = alpha * (1.0f - alpha_buf);
                    float4 cl = s_cl[i];
                    float om = 1.0f - na;
                    ir = ir * om + cl.x * na;
                    ig = ig * om + cl.y * na;
                    ib = ib * om + cl.z * na;
                    alpha_buf += na;
                    depth_buf = gm.z;
                }
            }
        }
        __syncthreads();
    }

    if (valid) {
        int bidx = (py * W + px) * 3;
        out[bidx + 0] = ir;
        out[bidx + 1] = ig;
        out[bidx + 2] = ib;
    }
}

extern "C" void kernel_launch(void* const* d_in, const int* in_sizes, int n_in,
                              void* d_out, int out_size)
{
    const float* means     = (const float*)d_in[0];
    const float* scales    = (const float*)d_in[1];
    const float* rots      = (const float*)d_in[2];
    const float* opacities = (const float*)d_in[3];
    const float* features  = (const float*)d_in[4];
    const float* pose      = (const float*)d_in[5];
    const float* focal_p   = (const float*)d_in[6];
    const float* cx_p      = (const float*)d_in[7];
    const float* cy_p      = (const float*)d_in[8];

    int N = in_sizes[0] / 3;

    // Derive (square) image dims from output size: out = H*W*3 floats.
    int hw = out_size / 3;
    int W = (int)(sqrtf((float)hw) + 0.5f);
    int H = hw / W;

    preprocess_kernel<<<(N + 255) / 256, 256>>>(
        means, scales, rots, opacities, features, pose,
        focal_p, cx_p, cy_p, N);

    dim3 blk(16, 8);
    dim3 grd((W + blk.x - 1) / blk.x, (H + blk.y - 1) / blk.y);
    render_kernel<<<grd, blk>>>((float*)d_out, N, W, H);
}